// round 11
// baseline (speedup 1.0000x reference)
#include <cuda_runtime.h>
#include <math_constants.h>

#define NB 15
#define MAXC 1024
#define L2E 1.4426950408889634f

// Single-instruction MUFU exp2 — immune to whether harness uses fast-math.
#define EX2(dst, src) asm("ex2.approx.ftz.f32 %0, %1;" : "=f"(dst) : "f"(src))
__device__ __forceinline__ float ex2f(float x) { float y; EX2(y, x); return y; }

// Scratch, bin-major: g_conf[b*MAXC + c]. Zero-initialized at load; the
// last block resets everything after finalizing so graph replays stay correct.
__device__ float g_conf[NB * MAXC];
__device__ float g_lab [NB * MAXC];
__device__ float g_correct[MAXC];
__device__ float g_total  [MAXC];
__device__ unsigned int g_ticket;

__device__ __forceinline__ float bnd(int i) {
    return (i >= 15) ? 1.0f : (float)i * (1.0f / 15.0f);
}

// searchsorted(bounds, p, 'left') - 1  for p in (1/15, 1]
__device__ __forceinline__ int bin_of(float p) {
    int k = (int)(p * 15.0f);
    if (k > 14) k = 14;
    if (k < 0)  k = 0;
    while (k > 0  && p <= bnd(k))     k--;
    while (k < 14 && p >  bnd(k + 1)) k++;
    return k;
}

// Two warps (64 threads) co-own ONE row per iteration; each thread owns 16
// classes (4 float4 segments, col = s*256 + tp*4). Next row prefetched into
// registers during the reduce. No argmax index is ever computed: accuracy
// uses exp-monotonicity — choice==label  <=>  ex2(x[lab]) == max(e) (exact,
// same deterministic ex2 of the same float). Rare p>1/15 elements handled
// by compensated atomics. Last block finalizes + resets scratch in-kernel.
__global__ __launch_bounds__(256, 4) void ece_main(
    const float* __restrict__ logits, const int* __restrict__ labels,
    float* __restrict__ out, int N, int C)
{
    __shared__ float2 s_ex[2][4][2];   // [buf][pair][warp] = (sum, max)
    __shared__ float  s_conf[MAXC];
    __shared__ bool   s_last;

    const int tid = threadIdx.x;
    for (int i = tid; i < MAXC; i += blockDim.x) s_conf[i] = 0.f;
    __syncthreads();

    const int lane  = tid & 31;
    const int pair  = tid >> 6;          // 0..3
    const int pw    = (tid >> 5) & 1;    // warp within pair
    const int tp    = tid & 63;          // thread within pair
    const int pid   = blockIdx.x * 4 + pair;
    const int npair = gridDim.x * 4;
    const int barid = 1 + pair;
    const float B1  = 1.0f / 15.0f;
    const float NEG = -CUDART_INF_F;
    const unsigned FULL = 0xffffffffu;

    float acc[16];
    #pragma unroll
    for (int i = 0; i < 16; i++) acc[i] = 0.f;

    // loop-invariant boundary: segs 0-2 always in-bounds (<=764 < C);
    // seg 3 only for threads with 768 + tp*4 + 4 <= C.
    const bool in3 = (768 + tp * 4 + 4 <= C);

    // OOB lanes keep NEG forever -> e = 0, never contribute.
    float4 nv[4];
    nv[0] = nv[1] = nv[2] = nv[3] = make_float4(NEG, NEG, NEG, NEG);

    const size_t stride = (size_t)npair * C;
    const float* rp = logits + (size_t)pid * C + tp * 4;   // thread base
    int r = pid;
    if (r < N) {
        nv[0] = *reinterpret_cast<const float4*>(rp);
        nv[1] = *reinterpret_cast<const float4*>(rp + 256);
        nv[2] = *reinterpret_cast<const float4*>(rp + 512);
        if (in3) nv[3] = *reinterpret_cast<const float4*>(rp + 768);
    }

    int it = 0;
    #pragma unroll 1
    for (; r < N; r += npair, ++it) {
        // consume prefetched row: single-MUFU exp in place
        float4 E[4];
        #pragma unroll
        for (int s = 0; s < 4; s++) {
            E[s].x = ex2f(nv[s].x * L2E);
            E[s].y = ex2f(nv[s].y * L2E);
            E[s].z = ex2f(nv[s].z * L2E);
            E[s].w = ex2f(nv[s].w * L2E);
        }

        // issue next row's loads NOW (overlap with reduce below)
        const float* rpn = rp + stride;
        if (r + npair < N) {
            nv[0] = *reinterpret_cast<const float4*>(rpn);
            nv[1] = *reinterpret_cast<const float4*>(rpn + 256);
            nv[2] = *reinterpret_cast<const float4*>(rpn + 512);
            if (in3) nv[3] = *reinterpret_cast<const float4*>(rpn + 768);
        }

        // per-thread sum + max(e)
        float sum = 0.f, me = 0.f;
        #pragma unroll
        for (int s = 0; s < 4; s++) {
            sum += (E[s].x + E[s].y) + (E[s].z + E[s].w);
            me = fmaxf(me, fmaxf(fmaxf(E[s].x, E[s].y), fmaxf(E[s].z, E[s].w)));
        }

        // warp reduce: f32 sum + f32 max only
        #pragma unroll
        for (int o = 16; o > 0; o >>= 1) {
            sum += __shfl_xor_sync(FULL, sum, o);
            me = fmaxf(me, __shfl_xor_sync(FULL, me, o));
        }

        // cross-warp exchange (double-buffered; one named 64-thread barrier)
        const int buf = it & 1;
        if (lane == 0) s_ex[buf][pair][pw] = make_float2(sum, me);
        asm volatile("bar.sync %0, 64;" :: "r"(barid) : "memory");

        const float2 e0 = s_ex[buf][pair][0];
        const float2 e1 = s_ex[buf][pair][1];
        const float rsum    = e0.x + e1.x;
        const float me_pair = fmaxf(e0.y, e1.y);
        const float rinv    = 1.0f / rsum;

        // per-row bookkeeping (thread 0 of pair); no index needed:
        // choice == label  <=>  ex2(x[lab]) == max(e)
        if (tp == 0) {
            const int lab = labels[r];
            atomicAdd(&g_total[lab], 1.f);
            const float el = ex2f(__ldg(rp + lab) * L2E);   // rp == row base
            if (el == me_pair) atomicAdd(&g_correct[lab], 1.f);
            const float p = el * rinv;
            if (p > 0.f) {
                const int k = (p > B1) ? bin_of(p) : 0;
                atomicAdd(&g_lab[k * MAXC + lab], 1.f);
            }
        }

        // accumulate: FFMA straight into bin-0 register accumulators
        #pragma unroll
        for (int s = 0; s < 4; s++) {
            acc[s*4+0] = fmaf(E[s].x, rinv, acc[s*4+0]);
            acc[s*4+1] = fmaf(E[s].y, rinv, acc[s*4+1]);
            acc[s*4+2] = fmaf(E[s].z, rinv, acc[s*4+2]);
            acc[s*4+3] = fmaf(E[s].w, rinv, acc[s*4+3]);
        }

        // rare slow path: exact row-uniform trigger via max(e)*rinv
        if (me_pair * rinv > B1) {
            #pragma unroll
            for (int s = 0; s < 4; s++) {
                const int col = s * 256 + tp * 4;
                const float pv[4] = { E[s].x * rinv, E[s].y * rinv,
                                      E[s].z * rinv, E[s].w * rinv };
                #pragma unroll
                for (int j = 0; j < 4; j++) {
                    if (pv[j] > B1) {
                        const int c = col + j;
                        const int k = bin_of(pv[j]);
                        atomicAdd(&g_conf[k * MAXC + c], pv[j]);
                        atomicAdd(&g_conf[c], -pv[j]);   // compensate bin 0
                    }
                }
            }
        }

        rp = rpn;
    }

    // flush: regs -> smem (block combine) -> one atomic/class/block
    #pragma unroll
    for (int s = 0; s < 4; s++) {
        const int col = s * 256 + tp * 4;
        #pragma unroll
        for (int j = 0; j < 4; j++)
            atomicAdd(&s_conf[col + j], acc[s*4+j]);
    }
    __syncthreads();
    for (int c = tid; c < C; c += blockDim.x) {
        const float v = s_conf[c];
        if (v != 0.f) atomicAdd(&g_conf[c], v);          // bin 0, coalesced
    }

    // completion ticket: last block finalizes + resets scratch
    __threadfence();
    __syncthreads();
    if (tid == 0)
        s_last = (atomicAdd(&g_ticket, 1u) == gridDim.x - 1);
    __syncthreads();
    if (!s_last) return;

    const float invN = 1.0f / (float)N;
    for (int c = tid; c < C; c += blockDim.x) {
        float s = 0.f;
        #pragma unroll
        for (int b = 0; b < NB; b++) {
            const float cf = __ldcg(&g_conf[b * MAXC + c]);
            const float lf = __ldcg(&g_lab [b * MAXC + c]);
            s += fabsf(cf - lf);
            g_conf[b * MAXC + c] = 0.f;
            g_lab [b * MAXC + c] = 0.f;
        }
        out[c]     = s * invN;
        out[C + c] = __ldcg(&g_correct[c]) / __ldcg(&g_total[c]);
        g_correct[c] = 0.f;
        g_total[c]   = 0.f;
    }
    if (tid == 0) g_ticket = 0;   // reset for next graph replay
}

extern "C" void kernel_launch(void* const* d_in, const int* in_sizes, int n_in,
                              void* d_out, int out_size) {
    const float* logits = (const float*)d_in[0];
    const int*   labels = (const int*)d_in[1];
    int N = in_sizes[1];
    int C = in_sizes[0] / N;   // 1000; assumes C <= 1024, multiple of 4

    // 148 SMs x 4 CTAs/SM = 592 resident blocks -> one wave at <=64 regs.
    ece_main<<<592, 256>>>(logits, labels, (float*)d_out, N, C);
}

// round 13
// speedup vs baseline: 1.1805x; 1.1805x over previous
#include <cuda_runtime.h>
#include <math_constants.h>

#define NB 15
#define MAXC 1024
#define L2E 1.4426950408889634f

// Single-instruction MUFU exp2 — immune to whether harness uses fast-math.
#define EX2(dst, src) asm("ex2.approx.ftz.f32 %0, %1;" : "=f"(dst) : "f"(src))
__device__ __forceinline__ float ex2f(float x) { float y; EX2(y, x); return y; }

// Scratch, bin-major: g_conf[b*MAXC + c]. Zero-initialized at load; finalize
// resets everything so graph replays stay correct. No allocation anywhere.
__device__ float g_conf[NB * MAXC];
__device__ float g_lab [NB * MAXC];
__device__ float g_correct[MAXC];
__device__ float g_total  [MAXC];

__device__ __forceinline__ float bnd(int i) {
    return (i >= 15) ? 1.0f : (float)i * (1.0f / 15.0f);
}

// searchsorted(bounds, p, 'left') - 1  for p in (1/15, 1]
__device__ __forceinline__ int bin_of(float p) {
    int k = (int)(p * 15.0f);
    if (k > 14) k = 14;
    if (k < 0)  k = 0;
    while (k > 0  && p <= bnd(k))     k--;
    while (k < 14 && p >  bnd(k + 1)) k++;
    return k;
}

// Two warps (64 threads) co-own ONE row per iteration; each thread owns 16
// classes (4 float4 segments, col = s*256 + tp*4). Next row prefetched into
// registers during the reduce. Warp reduce: 5-step interleaved shuffle
// (sum + max chains overlap). No argmax index: accuracy uses
// exp-monotonicity — choice==label <=> ex2(x[lab]) == max(e) (same
// deterministic ex2 of the same float, exact). Rare p>1/15 elements
// handled by compensated atomics.
__global__ __launch_bounds__(256, 4) void ece_main(
    const float* __restrict__ logits, const int* __restrict__ labels,
    int N, int C)
{
    __shared__ float2 s_ex[2][4][2];   // [buf][pair][warp] = (sum, max)
    __shared__ float  s_conf[MAXC];

    const int tid = threadIdx.x;
    for (int i = tid; i < MAXC; i += blockDim.x) s_conf[i] = 0.f;
    __syncthreads();

    const int lane  = tid & 31;
    const int pair  = tid >> 6;          // 0..3
    const int pw    = (tid >> 5) & 1;    // warp within pair
    const int tp    = tid & 63;          // thread within pair
    const int pid   = blockIdx.x * 4 + pair;
    const int npair = gridDim.x * 4;
    const int barid = 1 + pair;
    const float B1  = 1.0f / 15.0f;
    const float NEG = -CUDART_INF_F;
    const unsigned FULL = 0xffffffffu;

    float acc[16];
    #pragma unroll
    for (int i = 0; i < 16; i++) acc[i] = 0.f;

    // loop-invariant boundary: segs 0-2 always in-bounds (<=764 < C);
    // seg 3 only for threads with 768 + tp*4 + 4 <= C.
    const bool in3 = (768 + tp * 4 + 4 <= C);

    // OOB lanes keep NEG forever -> e = 0, never contribute.
    float4 nv[4];
    nv[0] = nv[1] = nv[2] = nv[3] = make_float4(NEG, NEG, NEG, NEG);

    const size_t stride = (size_t)npair * C;
    const float* rp = logits + (size_t)pid * C + tp * 4;   // thread base
    int r = pid;
    if (r < N) {
        nv[0] = *reinterpret_cast<const float4*>(rp);
        nv[1] = *reinterpret_cast<const float4*>(rp + 256);
        nv[2] = *reinterpret_cast<const float4*>(rp + 512);
        if (in3) nv[3] = *reinterpret_cast<const float4*>(rp + 768);
    }

    int it = 0;
    #pragma unroll 1
    for (; r < N; r += npair, ++it) {
        // consume prefetched row: single-MUFU exp in place
        float4 E[4];
        #pragma unroll
        for (int s = 0; s < 4; s++) {
            E[s].x = ex2f(nv[s].x * L2E);
            E[s].y = ex2f(nv[s].y * L2E);
            E[s].z = ex2f(nv[s].z * L2E);
            E[s].w = ex2f(nv[s].w * L2E);
        }

        // issue next row's loads NOW (overlap with reduce below)
        const float* rpn = rp + stride;
        if (r + npair < N) {
            nv[0] = *reinterpret_cast<const float4*>(rpn);
            nv[1] = *reinterpret_cast<const float4*>(rpn + 256);
            nv[2] = *reinterpret_cast<const float4*>(rpn + 512);
            if (in3) nv[3] = *reinterpret_cast<const float4*>(rpn + 768);
        }

        // per-thread sum + max(e)
        float sum = 0.f, me = 0.f;
        #pragma unroll
        for (int s = 0; s < 4; s++) {
            sum += (E[s].x + E[s].y) + (E[s].z + E[s].w);
            me = fmaxf(me, fmaxf(fmaxf(E[s].x, E[s].y), fmaxf(E[s].z, E[s].w)));
        }

        // warp reduce: interleaved butterfly (independent chains overlap)
        #pragma unroll
        for (int o = 16; o > 0; o >>= 1) {
            sum += __shfl_xor_sync(FULL, sum, o);
            me = fmaxf(me, __shfl_xor_sync(FULL, me, o));
        }

        // cross-warp exchange (double-buffered; one named 64-thread barrier)
        const int buf = it & 1;
        if (lane == 0) s_ex[buf][pair][pw] = make_float2(sum, me);
        asm volatile("bar.sync %0, 64;" :: "r"(barid) : "memory");

        const float2 e0 = s_ex[buf][pair][0];
        const float2 e1 = s_ex[buf][pair][1];
        const float rsum    = e0.x + e1.x;
        const float me_pair = fmaxf(e0.y, e1.y);
        const float rinv    = 1.0f / rsum;

        // per-row bookkeeping (thread 0 of pair); no index needed:
        // choice == label  <=>  ex2(x[lab]) == max(e)
        if (tp == 0) {
            const int lab = labels[r];
            atomicAdd(&g_total[lab], 1.f);
            const float el = ex2f(__ldg(rp + lab) * L2E);   // rp == row base
            if (el == me_pair) atomicAdd(&g_correct[lab], 1.f);
            const float p = el * rinv;
            if (p > 0.f) {
                const int k = (p > B1) ? bin_of(p) : 0;
                atomicAdd(&g_lab[k * MAXC + lab], 1.f);
            }
        }

        // accumulate: FFMA straight into bin-0 register accumulators
        #pragma unroll
        for (int s = 0; s < 4; s++) {
            acc[s*4+0] = fmaf(E[s].x, rinv, acc[s*4+0]);
            acc[s*4+1] = fmaf(E[s].y, rinv, acc[s*4+1]);
            acc[s*4+2] = fmaf(E[s].z, rinv, acc[s*4+2]);
            acc[s*4+3] = fmaf(E[s].w, rinv, acc[s*4+3]);
        }

        // rare slow path: exact row-uniform trigger via max(e)*rinv
        if (me_pair * rinv > B1) {
            #pragma unroll
            for (int s = 0; s < 4; s++) {
                const int col = s * 256 + tp * 4;
                const float pv[4] = { E[s].x * rinv, E[s].y * rinv,
                                      E[s].z * rinv, E[s].w * rinv };
                #pragma unroll
                for (int j = 0; j < 4; j++) {
                    if (pv[j] > B1) {
                        const int c = col + j;
                        const int k = bin_of(pv[j]);
                        atomicAdd(&g_conf[k * MAXC + c], pv[j]);
                        atomicAdd(&g_conf[c], -pv[j]);   // compensate bin 0
                    }
                }
            }
        }

        rp = rpn;
    }

    // flush: regs -> smem (block combine) -> one atomic/class/block
    #pragma unroll
    for (int s = 0; s < 4; s++) {
        const int col = s * 256 + tp * 4;
        #pragma unroll
        for (int j = 0; j < 4; j++)
            atomicAdd(&s_conf[col + j], acc[s*4+j]);
    }
    __syncthreads();
    for (int c = tid; c < C; c += blockDim.x) {
        const float v = s_conf[c];
        if (v != 0.f) atomicAdd(&g_conf[c], v);          // bin 0, coalesced
    }
}

// Parallel finalize: bin-major layout -> fully coalesced; also resets scratch.
__global__ void finalize_k(float* __restrict__ out, int N, int C) {
    const int c = blockIdx.x * blockDim.x + threadIdx.x;
    if (c >= C) return;
    float s = 0.f;
    #pragma unroll
    for (int b = 0; b < NB; b++) {
        s += fabsf(__ldcg(&g_conf[b * MAXC + c]) - __ldcg(&g_lab[b * MAXC + c]));
        g_conf[b * MAXC + c] = 0.f;
        g_lab [b * MAXC + c] = 0.f;
    }
    out[c]     = s / (float)N;
    out[C + c] = g_correct[c] / g_total[c];
    g_correct[c] = 0.f;
    g_total[c]   = 0.f;
}

extern "C" void kernel_launch(void* const* d_in, const int* in_sizes, int n_in,
                              void* d_out, int out_size) {
    const float* logits = (const float*)d_in[0];
    const int*   labels = (const int*)d_in[1];
    int N = in_sizes[1];
    int C = in_sizes[0] / N;   // 1000; assumes C <= 1024, multiple of 4

    // 148 SMs x 4 CTAs/SM = 592 resident blocks -> one wave at <=64 regs.
    ece_main<<<592, 256>>>(logits, labels, N, C);
    finalize_k<<<(C + 127) / 128, 128>>>((float*)d_out, N, C);
}